// round 16
// baseline (speedup 1.0000x reference)
#include <cuda_runtime.h>
#include <cuda_bf16.h>
#include <cstdint>

// DescriptorLoss: bf16 HMMA; A (=d0) from fragment-ready global layout,
// B (=d1) via smem + ldmatrix; unified single-launch conversion stage.
//   dot[b,p,q] = sum_d D0[b,d,p]*D1[b,d,q]
//   loss = mean(mask ? relu(1-dot)*250 : relu(dot-0.2))

#define HW    4096
#define DDIM  128
#define NB    2
#define BM    128
#define BN    128
#define NQT   (HW / BN)          // 32
#define NPT   (HW / BM)          // 32
#define NPART (NB * NPT * NQT)   // 2048

#define MTILES (HW / 16)         // 256
#define KTILES (DDIM / 16)       // 8

#define LDK   136                // padded k-stride (bf16 elems)
#define LDKB  (LDK * 2)          // 272 B row pitch

#define SM_B   0
#define SM_RED (BM * LDKB)                  // 34816
#define SM_TOT (SM_RED + 512 * 4)           // 36864

// A fragments: [b][mi][ki][32 uint4] (2 MB, L2-resident)
__device__ uint4 g_af[(size_t)NB * MTILES * KTILES * 32];
__device__ __nv_bfloat16 g_d1t[(size_t)NB * HW * DDIM];  // [b][hw][d]
__device__ float g_partials[NPART];
__device__ unsigned int g_count;    // zero-init

__device__ __forceinline__ uint32_t smem_u32(const void* p) {
    uint32_t a;
    asm("{ .reg .u64 t; cvta.to.shared.u64 t, %1; cvt.u32.u64 %0, t; }" : "=r"(a) : "l"(p));
    return a;
}

// ---------- stage 1 (single launch): d0 -> frag layout, d1 -> [hw][d] rows ----------
__global__ __launch_bounds__(256)
void conv_kernel(const float* __restrict__ d0, const float* __restrict__ d1)
{
    __shared__ float st[64][129];    // [hw_local][d]
    const int which = blockIdx.y & 1;         // 0: d0->frag, 1: d1->rows
    const int b     = blockIdx.y >> 1;
    const float* src = (which ? d1 : d0) + (size_t)b * DDIM * HW;

    const int hw0 = blockIdx.x * 64;
    const int tid = threadIdx.x;

    // load 128 d-rows x 64 hw fp32, transposed into smem
    #pragma unroll
    for (int it = 0; it < 32; it++) {
        int idx = it * 256 + tid;
        int d   = idx >> 6;
        int x   = idx & 63;
        st[x][d] = src[(size_t)d * HW + hw0 + x];
    }
    __syncthreads();

    if (which == 0) {
        // emit 4 mi-tiles x 8 ki-tiles x 128 words of mma A-fragments
        uint32_t* dst = (uint32_t*)g_af + (size_t)b * MTILES * KTILES * 128;
        #pragma unroll
        for (int it = 0; it < 16; it++) {
            int wt   = it * 256 + tid;
            int tile = wt >> 7;          // 0..31
            int w    = wt & 127;
            int lane = w >> 2;           // 0..31
            int reg  = w & 3;
            int r  = ((reg & 1) << 3) + (lane >> 2);
            int c0 = ((reg >> 1) << 3) + ((lane & 3) << 1);
            int mi_l = tile >> 3;        // 0..3
            int ki   = tile & 7;
            int row = mi_l * 16 + r;
            int col = ki * 16 + c0;
            __nv_bfloat162 v(__float2bfloat16(st[row][col]),
                             __float2bfloat16(st[row][col + 1]));
            dst[(size_t)(((hw0 >> 4) + mi_l) * KTILES + ki) * 128 + w] = *(uint32_t*)&v;
        }
    } else {
        // emit 64 hw-rows x 128 d bf16 (as 64 hw x 64 bf16x2 words)
        uint32_t* dst = (uint32_t*)g_d1t + ((size_t)b * HW + hw0) * (DDIM / 2);
        #pragma unroll
        for (int it = 0; it < 16; it++) {
            int idx = it * 256 + tid;    // 0..4095
            int x   = idx >> 6;          // hw row 0..63
            int dp  = idx & 63;          // d pair
            __nv_bfloat162 v(__float2bfloat16(st[x][2 * dp]),
                             __float2bfloat16(st[x][2 * dp + 1]));
            dst[(size_t)x * (DDIM / 2) + dp] = *(uint32_t*)&v;
        }
    }
}

// ---------- stage 2: GEMM + fused loss + fused final reduce ----------
__global__ __launch_bounds__(512, 2)
void desc_loss_hmma_kernel(const int* __restrict__ mask, float* __restrict__ out)
{
    extern __shared__ char smem[];
    float* red = (float*)(smem + SM_RED);
    const uint32_t sbase = smem_u32(smem);

    const int tid = threadIdx.x;
    const int wid = tid >> 5;
    const int lid = tid & 31;
    const int g   = lid >> 2;      // 0..7
    const int t   = lid & 3;       // 0..3

    const int b  = blockIdx.z;
    const int p0 = blockIdx.y * BM;
    const int q0 = blockIdx.x * BN;

    // ---- B prologue: LDG uint4 -> STS ----
    {
        const __nv_bfloat16* gB = g_d1t + (size_t)b * HW * DDIM + (size_t)q0 * DDIM;
        #pragma unroll
        for (int it = 0; it < 4; it++) {
            int i = it * 512 + tid;
            int r = i >> 4;          // 0..127
            int c = i & 15;          // 16B chunk
            uint4 vb = *(const uint4*)(gB + (size_t)r * DDIM + c * 8);
            *(uint4*)(smem + SM_B + r * LDKB + c * 16) = vb;
        }
    }
    __syncthreads();

    // 16 warps = 4(m) x 4(n), warp tile 32x32
    const int wm = wid & 3;
    const int wn = wid >> 2;

    // A fragment pointers (uint4): tiles (p0>>4)+wm*2 and +1
    const uint4* aP0 = g_af
        + ((size_t)((b * MTILES + (p0 >> 4) + wm * 2) * KTILES)) * 32 + lid;
    const uint4* aP1 = aP0 + KTILES * 32;

    // B ldmatrix per-lane base address
    const int brow = (lid & 7) + ((lid >> 4) & 1) * 8;
    const int bcol = ((lid >> 3) & 1) * 8;
    uint32_t bAddr[2];
    #pragma unroll
    for (int h = 0; h < 2; h++)
        bAddr[h] = sbase + SM_B + (uint32_t)(wn * 32 + h * 16 + brow) * LDKB + bcol * 2;

    float acc[2][4][4];
    #pragma unroll
    for (int i = 0; i < 2; i++)
        #pragma unroll
        for (int j = 0; j < 4; j++)
            #pragma unroll
            for (int u = 0; u < 4; u++)
                acc[i][j][u] = 0.0f;

    #pragma unroll
    for (int s = 0; s < 8; s++) {
        const uint32_t koff = (uint32_t)s * 32;
        uint4 a0 = aP0[s * 32];
        uint4 a1 = aP1[s * 32];
        uint32_t bf[4][2];
        #pragma unroll
        for (int h = 0; h < 2; h++)
            asm volatile("ldmatrix.sync.aligned.m8n8.x4.shared.b16 {%0,%1,%2,%3}, [%4];"
                         : "=r"(bf[2 * h][0]), "=r"(bf[2 * h][1]),
                           "=r"(bf[2 * h + 1][0]), "=r"(bf[2 * h + 1][1])
                         : "r"(bAddr[h] + koff));
        uint32_t afr[2][4] = {{a0.x, a0.y, a0.z, a0.w}, {a1.x, a1.y, a1.z, a1.w}};
        #pragma unroll
        for (int ti = 0; ti < 2; ti++)
            #pragma unroll
            for (int tj = 0; tj < 4; tj++) {
                asm volatile(
                    "mma.sync.aligned.m16n8k16.row.col.f32.bf16.bf16.f32 "
                    "{%0,%1,%2,%3}, {%4,%5,%6,%7}, {%8,%9}, {%0,%1,%2,%3};"
                    : "+f"(acc[ti][tj][0]), "+f"(acc[ti][tj][1]),
                      "+f"(acc[ti][tj][2]), "+f"(acc[ti][tj][3])
                    : "r"(afr[ti][0]), "r"(afr[ti][1]), "r"(afr[ti][2]), "r"(afr[ti][3]),
                      "r"(bf[tj][0]), "r"(bf[tj][1]));
            }
    }

    // ---- epilogue: fused hinge loss, mask loads batched per ti ----
    float lsum = 0.0f;
    {
        const int* mbase = mask + (size_t)b * HW * HW + q0;
        #pragma unroll
        for (int ti = 0; ti < 2; ti++) {
            const int pr0 = p0 + wm * 32 + ti * 16 + g;
            int2 m0[4], m1[4];
            #pragma unroll
            for (int tj = 0; tj < 4; tj++) {
                const int qc = wn * 32 + tj * 8 + 2 * t;
                m0[tj] = *(const int2*)(mbase + (size_t)pr0 * HW + qc);
                m1[tj] = *(const int2*)(mbase + (size_t)(pr0 + 8) * HW + qc);
            }
            #pragma unroll
            for (int tj = 0; tj < 4; tj++) {
                float dv, pos, neg;
                dv = acc[ti][tj][0];
                pos = fmaxf(0.0f, 1.0f - dv) * 250.0f; neg = fmaxf(0.0f, dv - 0.2f);
                lsum += m0[tj].x ? pos : neg;
                dv = acc[ti][tj][1];
                pos = fmaxf(0.0f, 1.0f - dv) * 250.0f; neg = fmaxf(0.0f, dv - 0.2f);
                lsum += m0[tj].y ? pos : neg;
                dv = acc[ti][tj][2];
                pos = fmaxf(0.0f, 1.0f - dv) * 250.0f; neg = fmaxf(0.0f, dv - 0.2f);
                lsum += m1[tj].x ? pos : neg;
                dv = acc[ti][tj][3];
                pos = fmaxf(0.0f, 1.0f - dv) * 250.0f; neg = fmaxf(0.0f, dv - 0.2f);
                lsum += m1[tj].y ? pos : neg;
            }
        }
    }

    // deterministic block reduction over 512 threads
    red[tid] = lsum;
    __syncthreads();
    #pragma unroll
    for (int s = 256; s > 0; s >>= 1) {
        if (tid < s) red[tid] += red[tid + s];
        __syncthreads();
    }

    // last CTA does the fixed-order final reduction
    __shared__ int is_last;
    if (tid == 0) {
        g_partials[(b * NPT + blockIdx.y) * NQT + blockIdx.x] = red[0];
        __threadfence();
        unsigned int v = atomicAdd(&g_count, 1u);
        is_last = (v == NPART - 1);
    }
    __syncthreads();
    if (is_last) {
        float s = (g_partials[tid] + g_partials[tid + 512])
                + (g_partials[tid + 1024] + g_partials[tid + 1536]);
        red[tid] = s;
        __syncthreads();
        #pragma unroll
        for (int st = 256; st > 0; st >>= 1) {
            if (tid < st) red[tid] += red[tid + st];
            __syncthreads();
        }
        if (tid == 0) {
            out[0] = red[0] * (1.0f / ((float)NB * (float)HW * (float)HW));
            g_count = 0;   // reset for next graph replay
        }
    }
}

extern "C" void kernel_launch(void* const* d_in, const int* in_sizes, int n_in,
                              void* d_out, int out_size)
{
    const float* d0   = (const float*)d_in[0];
    const float* d1   = (const float*)d_in[1];
    const int*   mask = (const int*)d_in[2];
    float*       out  = (float*)d_out;

    cudaFuncSetAttribute(desc_loss_hmma_kernel,
                         cudaFuncAttributeMaxDynamicSharedMemorySize, SM_TOT);

    conv_kernel<<<dim3(HW / 64, 2 * NB), 256>>>(d0, d1);
    desc_loss_hmma_kernel<<<dim3(NQT, NPT, NB), 512, SM_TOT>>>(mask, out);
}

// round 17
// speedup vs baseline: 1.1008x; 1.1008x over previous
#include <cuda_runtime.h>
#include <cuda_bf16.h>
#include <cstdint>

// DescriptorLoss: bf16 HMMA + ldmatrix; mask read coalesced per warp tile and
// redistributed to fragment order via ballot+shfl (no scattered mask LDG).
//   dot[b,p,q] = sum_d D0[b,d,p]*D1[b,d,q]
//   loss = mean(mask ? relu(1-dot)*250 : relu(dot-0.2))

#define HW    4096
#define DDIM  128
#define NB    2
#define BM    128
#define BN    128
#define NQT   (HW / BN)          // 32
#define NPT   (HW / BM)          // 32
#define NPART (NB * NPT * NQT)   // 2048

#define LDK   136                // padded k-stride (bf16 elems)
#define LDKB  (LDK * 2)          // 272 B row pitch

#define SM_A   0
#define SM_B   (BM * LDKB)                  // 34816
#define SM_RED (SM_B + BN * LDKB)           // 69632
#define SM_TOT (SM_RED + 512 * 4)           // 71680

__device__ __nv_bfloat16 g_d0t[(size_t)NB * HW * DDIM];  // [b][hw][d]
__device__ __nv_bfloat16 g_d1t[(size_t)NB * HW * DDIM];
__device__ float g_partials[NPART];
__device__ unsigned int g_count;                          // zero-init

__device__ __forceinline__ uint32_t smem_u32(const void* p) {
    uint32_t a;
    asm("{ .reg .u64 t; cvta.to.shared.u64 t, %1; cvt.u32.u64 %0, t; }" : "=r"(a) : "l"(p));
    return a;
}

// ---------- stage 1: convert + transpose ----------
__global__ __launch_bounds__(256)
void conv_kernel(const float* __restrict__ d0, const float* __restrict__ d1)
{
    __shared__ float tile[32][33];
    const int which = blockIdx.z & 1;
    const int b     = blockIdx.z >> 1;
    const float* src = (which ? d1 : d0) + (size_t)b * DDIM * HW;
    __nv_bfloat16* dst = (which ? g_d1t : g_d0t) + (size_t)b * HW * DDIM;

    const int hw0 = blockIdx.x * 32;
    const int dd0 = blockIdx.y * 32;
    const int tx = threadIdx.x, ty = threadIdx.y;   // 32 x 8

    #pragma unroll
    for (int j = 0; j < 4; j++)
        tile[ty + 8 * j][tx] = src[(size_t)(dd0 + ty + 8 * j) * HW + hw0 + tx];
    __syncthreads();
    #pragma unroll
    for (int j = 0; j < 4; j++)
        dst[(size_t)(hw0 + ty + 8 * j) * DDIM + dd0 + tx] =
            __float2bfloat16(tile[tx][ty + 8 * j]);
}

// ---------- stage 2: GEMM + fused loss + fused final reduce ----------
__global__ __launch_bounds__(512, 2)
void desc_loss_hmma_kernel(const int* __restrict__ mask, float* __restrict__ out)
{
    extern __shared__ char smem[];
    float* red = (float*)(smem + SM_RED);
    const uint32_t sbase = smem_u32(smem);

    const int tid = threadIdx.x;
    const int wid = tid >> 5;
    const int lid = tid & 31;

    const int b  = blockIdx.z;
    const int p0 = blockIdx.y * BM;
    const int q0 = blockIdx.x * BN;

    // ---- desc prologue: LDG uint4 -> STS ----
    {
        const __nv_bfloat16* gA = g_d0t + (size_t)b * HW * DDIM + (size_t)p0 * DDIM;
        const __nv_bfloat16* gB = g_d1t + (size_t)b * HW * DDIM + (size_t)q0 * DDIM;
        #pragma unroll
        for (int it = 0; it < 4; it++) {
            int i = it * 512 + tid;
            int r = i >> 4;          // 0..127
            int c = i & 15;          // 16B chunk
            uint4 va = *(const uint4*)(gA + (size_t)r * DDIM + c * 8);
            uint4 vb = *(const uint4*)(gB + (size_t)r * DDIM + c * 8);
            *(uint4*)(smem + SM_A + r * LDKB + c * 16) = va;
            *(uint4*)(smem + SM_B + r * LDKB + c * 16) = vb;
        }
    }
    __syncthreads();

    // 16 warps = 4(m) x 4(n), warp tile 32x32
    const int wm = wid & 3;
    const int wn = wid >> 2;

    // ldmatrix per-lane base addresses
    const uint32_t sA = sbase + SM_A;
    const uint32_t sB = sbase + SM_B;
    const int arow = (lid & 7) + ((lid >> 3) & 1) * 8;
    const int acol = ((lid >> 4) & 1) * 8;
    uint32_t aAddr[2], bAddr[2];
    #pragma unroll
    for (int ti = 0; ti < 2; ti++)
        aAddr[ti] = sA + (uint32_t)(wm * 32 + ti * 16 + arow) * LDKB + acol * 2;
    const int brow = (lid & 7) + ((lid >> 4) & 1) * 8;
    const int bcol = ((lid >> 3) & 1) * 8;
    #pragma unroll
    for (int h = 0; h < 2; h++)
        bAddr[h] = sB + (uint32_t)(wn * 32 + h * 16 + brow) * LDKB + bcol * 2;

    float acc[2][4][4];
    #pragma unroll
    for (int i = 0; i < 2; i++)
        #pragma unroll
        for (int j = 0; j < 4; j++)
            #pragma unroll
            for (int u = 0; u < 4; u++)
                acc[i][j][u] = 0.0f;

    #pragma unroll
    for (int s = 0; s < 8; s++) {
        const uint32_t koff = (uint32_t)s * 32;
        uint32_t af[2][4], bf[4][2];
        #pragma unroll
        for (int ti = 0; ti < 2; ti++)
            asm volatile("ldmatrix.sync.aligned.m8n8.x4.shared.b16 {%0,%1,%2,%3}, [%4];"
                         : "=r"(af[ti][0]), "=r"(af[ti][1]), "=r"(af[ti][2]), "=r"(af[ti][3])
                         : "r"(aAddr[ti] + koff));
        #pragma unroll
        for (int h = 0; h < 2; h++)
            asm volatile("ldmatrix.sync.aligned.m8n8.x4.shared.b16 {%0,%1,%2,%3}, [%4];"
                         : "=r"(bf[2 * h][0]), "=r"(bf[2 * h][1]),
                           "=r"(bf[2 * h + 1][0]), "=r"(bf[2 * h + 1][1])
                         : "r"(bAddr[h] + koff));
        #pragma unroll
        for (int ti = 0; ti < 2; ti++)
            #pragma unroll
            for (int tj = 0; tj < 4; tj++) {
                asm volatile(
                    "mma.sync.aligned.m16n8k16.row.col.f32.bf16.bf16.f32 "
                    "{%0,%1,%2,%3}, {%4,%5,%6,%7}, {%8,%9}, {%0,%1,%2,%3};"
                    : "+f"(acc[ti][tj][0]), "+f"(acc[ti][tj][1]),
                      "+f"(acc[ti][tj][2]), "+f"(acc[ti][tj][3])
                    : "r"(af[ti][0]), "r"(af[ti][1]), "r"(af[ti][2]), "r"(af[ti][3]),
                      "r"(bf[tj][0]), "r"(bf[tj][1]));
            }
    }

    // ---- epilogue: coalesced warp-tile mask load + ballot pack + shfl consume ----
    float lsum = 0.0f;
    {
        // warp's 32x32 mask tile; lane lid loads rows {i*4 + (lid>>3)}, 16B at col (lid&7)*4
        const int* mwarp = mask + (size_t)b * HW * HW
                         + (size_t)(p0 + wm * 32 + (lid >> 3)) * HW
                         + q0 + wn * 32 + (lid & 7) * 4;

        // ballot p = element p of every lane; lane L keeps B_L.
        // element p of lane L = mask[(p>>2)*4 + (L>>3)][(L&7)*4 + (p&3)]
        uint32_t keep = 0;
        #pragma unroll
        for (int half = 0; half < 2; half++) {
            uint4 m[4];
            #pragma unroll
            for (int i = 0; i < 4; i++)
                m[i] = *(const uint4*)(mwarp + (size_t)(half * 16 + i * 4) * HW);
            #pragma unroll
            for (int i = 0; i < 4; i++) {
                const int p = (half * 4 + i) * 4;
                uint32_t b0 = __ballot_sync(0xffffffffu, m[i].x != 0);
                uint32_t b1 = __ballot_sync(0xffffffffu, m[i].y != 0);
                uint32_t b2 = __ballot_sync(0xffffffffu, m[i].z != 0);
                uint32_t b3 = __ballot_sync(0xffffffffu, m[i].w != 0);
                keep = (lid == p + 0) ? b0 : keep;
                keep = (lid == p + 1) ? b1 : keep;
                keep = (lid == p + 2) ? b2 : keep;
                keep = (lid == p + 3) ? b3 : keep;
            }
        }

        // consume: lane needs mask[r][c] with r = ti*16 + g + 8*(u>=2),
        // c = tj*8 + 2t + (u&1)  (g = lid>>2, t = lid&3).
        // word index e = 16*ti + 8*(u>>1) + (u&1) + 4*((lid>>4)&1) + 2*(lid&1)
        // bit index   h = (g&3)*8 + (t>>1) + 2*tj
        const int hbase = ((lid >> 2) & 3) * 8 + ((lid & 3) >> 1);
        const int eoff  = 4 * ((lid >> 4) & 1) + 2 * (lid & 1);
        #pragma unroll
        for (int ti = 0; ti < 2; ti++)
            #pragma unroll
            for (int u = 0; u < 4; u++) {
                const int e = 16 * ti + 8 * (u >> 1) + (u & 1) + eoff;
                uint32_t Be = __shfl_sync(0xffffffffu, keep, e);
                #pragma unroll
                for (int tj = 0; tj < 4; tj++) {
                    float dv  = acc[ti][tj][u];
                    float pos = fmaxf(0.0f, 1.0f - dv) * 250.0f;
                    float neg = fmaxf(0.0f, dv - 0.2f);
                    lsum += ((Be >> (hbase + 2 * tj)) & 1u) ? pos : neg;
                }
            }
    }

    // deterministic block reduction over 512 threads
    red[tid] = lsum;
    __syncthreads();
    #pragma unroll
    for (int s = 256; s > 0; s >>= 1) {
        if (tid < s) red[tid] += red[tid + s];
        __syncthreads();
    }

    // last CTA does the fixed-order final reduction
    __shared__ int is_last;
    if (tid == 0) {
        g_partials[(b * NPT + blockIdx.y) * NQT + blockIdx.x] = red[0];
        __threadfence();
        unsigned int v = atomicAdd(&g_count, 1u);
        is_last = (v == NPART - 1);
    }
    __syncthreads();
    if (is_last) {
        float s = (g_partials[tid] + g_partials[tid + 512])
                + (g_partials[tid + 1024] + g_partials[tid + 1536]);
        red[tid] = s;
        __syncthreads();
        #pragma unroll
        for (int st = 256; st > 0; st >>= 1) {
            if (tid < st) red[tid] += red[tid + st];
            __syncthreads();
        }
        if (tid == 0) {
            out[0] = red[0] * (1.0f / ((float)NB * (float)HW * (float)HW));
            g_count = 0;   // reset for next graph replay
        }
    }
}

extern "C" void kernel_launch(void* const* d_in, const int* in_sizes, int n_in,
                              void* d_out, int out_size)
{
    const float* d0   = (const float*)d_in[0];
    const float* d1   = (const float*)d_in[1];
    const int*   mask = (const int*)d_in[2];
    float*       out  = (float*)d_out;

    cudaFuncSetAttribute(desc_loss_hmma_kernel,
                         cudaFuncAttributeMaxDynamicSharedMemorySize, SM_TOT);

    conv_kernel<<<dim3(HW / 32, DDIM / 32, 2 * NB), dim3(32, 8)>>>(d0, d1);
    desc_loss_hmma_kernel<<<dim3(NQT, NPT, NB), 512, SM_TOT>>>(mask, out);
}